// round 4
// baseline (speedup 1.0000x reference)
#include <cuda_runtime.h>
#include <cuda_bf16.h>

// Problem constants (fixed by the dataset):
//   N = 55440*1024 = 56,770,560 fp32; candidates L in [4,32] dividing N -> 20
//   P = lcm(candidates) = 110880, N / P = 512
#define NTOT   56770560
#define PP4    27720        // P/4 float4 positions per period
#define RSPLIT 8            // split the 512 repeats 8 ways for occupancy
#define RCHUNK 64           // 512 / RSPLIT
#define NCAND  20
#define NBX    109          // ceil(PP4 / 256)
#define NBLK   (NBX * RSPLIT)   // 872 blocks; wave1 = 592 resident @4/SM

// Scratch (__device__ globals; plain per-block stores -> no init required)
__device__ unsigned g_blk[NBLK][NCAND];  // per-block candidate maxima (float bits)
__device__ unsigned g_done;             // completion counter, self-resets to 0

// ---------------------------------------------------------------------------
// Single fused kernel.
// Phase A: thread t (float4 position), chunk c=blockIdx.y: streaming min/max
//          over RCHUNK repeats (coalesced 512B warp loads, read-once __ldcs).
// Phase B: evaluate all 20 candidates on the chunk-local (mn, mx). Valid since
//          max over (p, r) = max over chunks of the per-chunk candidate max,
//          and max_v |fl(v-c)| = max(fl(mx-c), fl(c-mn)) exactly (fl monotone,
//          sign-symmetric). pat = x[p % L], L a literal after unroll.
// Phase C: shfl-butterfly warp reduce -> lane-0 shared atomics -> per-block
//          plain store to g_blk. Last block reduces g_blk, computes scores,
//          argmax, writes 42 outputs. Counter resets for graph replay.
// ---------------------------------------------------------------------------
__global__ __launch_bounds__(256, 4) void pm_fused(const float4* __restrict__ x4,
                                                   float* __restrict__ out,
                                                   int out_size) {
    __shared__ float    s_pat[32];
    __shared__ unsigned s_max[NCAND];
    __shared__ bool     s_last;
    if (threadIdx.x < 32)    s_pat[threadIdx.x] = ((const float*)x4)[threadIdx.x];
    if (threadIdx.x < NCAND) s_max[threadIdx.x] = 0u;
    __syncthreads();

    const int LENS[NCAND] = {4,5,6,7,8,9,10,11,12,14,15,16,18,20,21,22,24,28,30,32};

    float acc[NCAND];
#pragma unroll
    for (int k = 0; k < NCAND; k++) acc[k] = 0.0f;

    int t = blockIdx.x * 256 + threadIdx.x;
    if (t < PP4) {
        // --- Phase A: chunk-local min/max over RCHUNK repeats ---
        const float4* p = x4 + (size_t)blockIdx.y * (RCHUNK * PP4) + t;
        float4 v = __ldcs(p);
        float4 mn = v, mx = v;
#pragma unroll 8
        for (int r = 1; r < RCHUNK; r++) {
            float4 u = __ldcs(p + r * PP4);
            mn.x = fminf(mn.x, u.x); mx.x = fmaxf(mx.x, u.x);
            mn.y = fminf(mn.y, u.y); mx.y = fmaxf(mx.y, u.y);
            mn.z = fminf(mn.z, u.z); mx.z = fmaxf(mx.z, u.z);
            mn.w = fminf(mn.w, u.w); mx.w = fmaxf(mx.w, u.w);
        }

        // --- Phase B: 20-candidate fold on this thread's 4 positions ---
        float mnk[4] = {mn.x, mn.y, mn.z, mn.w};
        float mxk[4] = {mx.x, mx.y, mx.z, mx.w};
        int p0 = 4 * t;
#pragma unroll
        for (int j = 0; j < 4; j++) {
            int pp = p0 + j;
#pragma unroll
            for (int k = 0; k < NCAND; k++) {
                int   L   = LENS[k];                 // literal after unroll
                float ctr = s_pat[pp % L];
                float d   = fmaxf(mxk[j] - ctr, ctr - mnk[j]);
                acc[k]    = fmaxf(acc[k], d);
            }
        }
    }

    // --- Phase C: warp shfl reduce, lane-0 shared atomics, per-block store ---
#pragma unroll
    for (int k = 0; k < NCAND; k++) {
        float a = acc[k];
        a = fmaxf(a, __shfl_xor_sync(0xFFFFFFFFu, a, 16));
        a = fmaxf(a, __shfl_xor_sync(0xFFFFFFFFu, a, 8));
        a = fmaxf(a, __shfl_xor_sync(0xFFFFFFFFu, a, 4));
        a = fmaxf(a, __shfl_xor_sync(0xFFFFFFFFu, a, 2));
        a = fmaxf(a, __shfl_xor_sync(0xFFFFFFFFu, a, 1));
        acc[k] = a;
    }
    if ((threadIdx.x & 31) == 0) {
#pragma unroll
        for (int k = 0; k < NCAND; k++)
            atomicMax(&s_max[k], __float_as_uint(acc[k]));
    }
    __syncthreads();

    int bid = blockIdx.y * gridDim.x + blockIdx.x;
    if (threadIdx.x < NCAND)
        g_blk[bid][threadIdx.x] = s_max[threadIdx.x];

    __threadfence();   // publish g_blk before signaling completion
    if (threadIdx.x == 0) {
        unsigned prev = atomicAdd(&g_done, 1u);
        s_last = (prev == NBLK - 1);
    }
    __syncthreads();
    if (!s_last) return;

    // --- Finalize (one block): reduce g_blk, scores, argmax, outputs ---
    __threadfence();   // acquire all writers' g_blk stores
    __shared__ unsigned s_fin[NCAND];
    if (threadIdx.x == 0) g_done = 0u;            // reset for next replay
    if (threadIdx.x < NCAND) s_fin[threadIdx.x] = 0u;
    __syncthreads();

    if (threadIdx.x < 240) {                      // 12 groups x 20 candidates
        int g = threadIdx.x / NCAND;
        int k = threadIdx.x % NCAND;
        unsigned v = 0u;
        for (int b = g; b < NBLK; b += 12)
            v = max(v, g_blk[b][k]);
        atomicMax(&s_fin[k], v);
    }
    __syncthreads();

    if (threadIdx.x == 0) {
        float best = 0.0f;
        int   bidx = 0;
#pragma unroll
        for (int k = 0; k < NCAND; k++) {
            float md  = __uint_as_float(s_fin[k]);
            int   L   = LENS[k];
            float raw = (float)((double)(NTOT / L) / (double)L);
            float eff = (md < 0.01f) ? raw : 0.0f;
            if (k < out_size)      out[k]      = md;
            if (20 + k < out_size) out[20 + k] = eff;
            if (eff > best) { best = eff; bidx = k; }  // first max, like jnp.argmax
        }
        if (out_size > 40) out[40] = (float)bidx;
        if (out_size > 41) out[41] = best;
    }
}

// ---------------------------------------------------------------------------
extern "C" void kernel_launch(void* const* d_in, const int* in_sizes, int n_in,
                              void* d_out, int out_size) {
    const float* x = (const float*)d_in[0];
    float* out = (float*)d_out;

    dim3 grid(NBX, RSPLIT);
    pm_fused<<<grid, 256>>>((const float4*)x, out, out_size);
}